// round 7
// baseline (speedup 1.0000x reference)
#include <cuda_runtime.h>
#include <cuda_bf16.h>
#include <math.h>
#include <stdint.h>

#define BB 64
#define FF 256
#define TT 1024
#define HH 1024
#define OO 512
#define NB 128   // persistent CTAs: 4 batch-row groups x 32 H-col tiles (<=148 -> co-resident)

// Scratch (allocation-free rule: __device__ globals)
__device__ float g_Z[(size_t)TT * BB * HH];     // Z = x@Wx + b, later overwritten with states, [t][b][h]
__device__ float g_ST2[2][4][HH * 16];          // transposed state ping-pong, [buf][r-group][h][16 b]
__device__ unsigned g_cnt4[4 * 32];             // per-r-group barrier counters (128B apart)
__device__ unsigned g_gen4[4 * 32];             // per-r-group barrier generations (128B apart)

// ---------------------------------------------------------------- helpers
__device__ __forceinline__ float2 ffma2(float2 a, float2 b, float2 c) {
    unsigned long long ua = *reinterpret_cast<unsigned long long*>(&a);
    unsigned long long ub = *reinterpret_cast<unsigned long long*>(&b);
    unsigned long long uc = *reinterpret_cast<unsigned long long*>(&c);
    unsigned long long ud;
    asm("fma.rn.f32x2 %0, %1, %2, %3;" : "=l"(ud) : "l"(ua), "l"(ub), "l"(uc));
    return *reinterpret_cast<float2*>(&ud);
}
__device__ __forceinline__ float2 dup2(float s) { return make_float2(s, s); }

__device__ __forceinline__ void cp_async16(float* smem_dst, const float* gmem_src) {
    unsigned s = (unsigned)__cvta_generic_to_shared(smem_dst);
    asm volatile("cp.async.cg.shared.global [%0], [%1], 16;\n" :: "r"(s), "l"(gmem_src));
}
__device__ __forceinline__ void cp_commit() { asm volatile("cp.async.commit_group;\n"); }
template <int N> __device__ __forceinline__ void cp_wait() {
    asm volatile("cp.async.wait_group %0;\n" :: "n"(N));
}

__device__ __forceinline__ void mbar_init(uint32_t mb, uint32_t count) {
    asm volatile("mbarrier.init.shared.b64 [%0], %1;" :: "r"(mb), "r"(count) : "memory");
}
__device__ __forceinline__ void mbar_expect_tx(uint32_t mb, uint32_t bytes) {
    asm volatile("mbarrier.arrive.expect_tx.shared.b64 _, [%0], %1;" :: "r"(mb), "r"(bytes) : "memory");
}
__device__ __forceinline__ void bulk_g2s(uint32_t dst_smem, const float* src, uint32_t bytes, uint32_t mb) {
    asm volatile("cp.async.bulk.shared::cluster.global.mbarrier::complete_tx::bytes [%0], [%1], %2, [%3];"
                 :: "r"(dst_smem), "l"(src), "r"(bytes), "r"(mb) : "memory");
}
__device__ __forceinline__ void mbar_wait(uint32_t mb, int ph) {
    asm volatile(
        "{\n\t"
        ".reg .pred P;\n\t"
        "W%=:\n\t"
        "mbarrier.try_wait.parity.acquire.cta.shared::cta.b64 P, [%0], %1, 0x989680;\n\t"
        "@P bra D%=;\n\t"
        "bra W%=;\n\t"
        "D%=:\n\t"
        "}" :: "r"(mb), "r"(ph) : "memory");
}

// barrier among the 32 CTAs of one r-group (independent dependency domains)
__device__ __forceinline__ void group_barrier(int r) {
    __syncthreads();
    if (threadIdx.x == 0) {
        unsigned* cnt = &g_cnt4[r * 32];
        unsigned* gen = &g_gen4[r * 32];
        unsigned g;
        asm volatile("ld.acquire.gpu.global.u32 %0, [%1];" : "=r"(g) : "l"(gen) : "memory");
        asm volatile("fence.acq_rel.gpu;" ::: "memory");
        unsigned prev = atomicAdd(cnt, 1u);
        if (prev == 31u) {
            *cnt = 0u;
            unsigned ng = g + 1u;
            asm volatile("st.release.gpu.global.u32 [%0], %1;" :: "l"(gen), "r"(ng) : "memory");
        } else {
            unsigned cur;
            do {
                __nanosleep(32);
                asm volatile("ld.acquire.gpu.global.u32 %0, [%1];" : "=r"(cur) : "l"(gen) : "memory");
            } while (cur == g);
        }
    }
    __syncthreads();
}

// ---------------------------------------------------------------- Kernel A: Z[t][b][h] = b[h] + sum_f x[b][f][t] * Wx[f][h]
__global__ void __launch_bounds__(256) zmat_kernel(const float* __restrict__ x,
                                                   const float* __restrict__ Wx,
                                                   const float* __restrict__ bias) {
    extern __shared__ float dsm[];
    float* xs = dsm;           // [2][32][128]
    float* ws = dsm + 8192;    // [2][32][128]
    int t0 = blockIdx.x * 128;
    int h0 = blockIdx.y * 128;
    int b  = blockIdx.z;
    int tid = threadIdx.x;
    int tt = tid >> 4;
    int th = tid & 15;
    const float* xb = x + (size_t)b * FF * TT;

    float2 acc[8][4];
    #pragma unroll
    for (int i = 0; i < 8; i++)
        #pragma unroll
        for (int j = 0; j < 4; j++) acc[i][j] = make_float2(0.f, 0.f);

    auto issue = [&](int ci, int buf) {
        int f0 = ci * 32;
        float* xd = xs + buf * 4096;
        float* wd = ws + buf * 4096;
        #pragma unroll
        for (int it = 0; it < 4; it++) {
            int idx = it * 256 + tid;
            int f = idx >> 5, u = (idx & 31) * 4;
            cp_async16(xd + f * 128 + u, xb + (f0 + f) * TT + t0 + u);
            cp_async16(wd + f * 128 + u, Wx + (f0 + f) * HH + h0 + u);
        }
        cp_commit();
    };

    issue(0, 0);
    for (int ci = 0; ci < 8; ci++) {
        if (ci < 7) { issue(ci + 1, (ci + 1) & 1); cp_wait<1>(); }
        else cp_wait<0>();
        __syncthreads();
        const float* xc = xs + (ci & 1) * 4096;
        const float* wc = ws + (ci & 1) * 4096;
        #pragma unroll
        for (int k = 0; k < 32; k++) {
            float4 a0 = *reinterpret_cast<const float4*>(xc + k * 128 + tt * 8);
            float4 a1 = *reinterpret_cast<const float4*>(xc + k * 128 + tt * 8 + 4);
            float4 w0 = *reinterpret_cast<const float4*>(wc + k * 128 + th * 8);
            float4 w1 = *reinterpret_cast<const float4*>(wc + k * 128 + th * 8 + 4);
            float2 wp[4] = { make_float2(w0.x, w0.y), make_float2(w0.z, w0.w),
                             make_float2(w1.x, w1.y), make_float2(w1.z, w1.w) };
            float av[8] = { a0.x, a0.y, a0.z, a0.w, a1.x, a1.y, a1.z, a1.w };
            #pragma unroll
            for (int i = 0; i < 8; i++) {
                float2 ad = dup2(av[i]);
                #pragma unroll
                for (int j = 0; j < 4; j++) acc[i][j] = ffma2(ad, wp[j], acc[i][j]);
            }
        }
        __syncthreads();
    }
    float4 bv0 = *reinterpret_cast<const float4*>(bias + h0 + th * 8);
    float4 bv1 = *reinterpret_cast<const float4*>(bias + h0 + th * 8 + 4);
    #pragma unroll
    for (int i = 0; i < 8; i++) {
        int t = t0 + tt * 8 + i;
        float* zp = g_Z + (size_t)t * (BB * HH) + b * HH + h0 + th * 8;
        float4 o0 = make_float4(acc[i][0].x + bv0.x, acc[i][0].y + bv0.y,
                                acc[i][1].x + bv0.z, acc[i][1].y + bv0.w);
        float4 o1 = make_float4(acc[i][2].x + bv1.x, acc[i][2].y + bv1.y,
                                acc[i][3].x + bv1.z, acc[i][3].y + bv1.w);
        *reinterpret_cast<float4*>(zp)     = o0;
        *reinterpret_cast<float4*>(zp + 4) = o1;
    }
}

// ---------------------------------------------------------------- Kernel B: persistent recurrence
// 128 CTAs: (r in 0..3: 16 batch rows) x (c in 0..31: 32 H cols). Per-r-group barriers.
// 512 threads = 16 warps = 4 warps/SMSP for latency hiding. K-split 16:
// warp w -> chunk ch=w>>2 (mbarrier), quarter q=w&3, k-range [ch*256+q*64, +64).
// One warp per chunk per SMSP -> chunk TMA arrivals overlap earlier chunks' FMA.
__global__ void __launch_bounds__(512, 1) rnn_rec_kernel(const float* __restrict__ Wh) {
    extern __shared__ float smem[];
    float* wh_s  = smem + 16;               // [k][32]  32768 floats (128KB)
    float* st_s  = wh_s + 32768;            // [k][16]  16384 floats (64KB)
    float* red_s = st_s + 16384;            // [16][512] 8192 floats (32KB)
    float* fin   = red_s + 8192;            // [16][33]   528 floats
    uint32_t mbar0 = (uint32_t)__cvta_generic_to_shared(smem);

    int tid  = threadIdx.x;
    int wid  = tid >> 5, lane = tid & 31;
    int c = blockIdx.x & 31;                // column tile (32 cols)
    int r = blockIdx.x >> 5;                // batch row group (16 rows)
    int r16 = r * 16;

    if (tid == 0) {
        #pragma unroll
        for (int ch = 0; ch < 4; ch++) mbar_init(mbar0 + ch * 8, 1);
    }
    for (int i = tid; i < 32768; i += 512) {
        int k = i >> 5, n = i & 31;
        wh_s[i] = Wh[k * HH + c * 32 + n];
    }
    __syncthreads();

    int rg = lane >> 3;                     // b-group: rows 4*rg..4*rg+3
    int cg = lane & 7;                      // h-group: cols 4*cg..4*cg+3
    int ch = wid >> 2;                      // chunk this warp consumes
    int kb = ch * 256 + (wid & 3) * 64;     // this warp's 64-k slice
    uint32_t mymb = mbar0 + ch * 8;

    // epilogue: 1 output scalar per thread (512 outputs = 16b x 32h)
    int o  = tid;
    int em = o >> 5, en = o & 31;
    int brow = r16 + em, hcol = c * 32 + en;
    // transposed-store mapping
    int hl = tid >> 4, em2 = tid & 15;

    float* zbase = g_Z + (size_t)brow * HH + hcol;

    for (int t = 0; t < TT; ++t) {
        // prefetch additive Z term for this step (hidden behind the FMA loop)
        float zq = zbase[(size_t)t * (BB * HH)];

        float2 acc[4][2];
        #pragma unroll
        for (int i = 0; i < 4; i++) { acc[i][0] = make_float2(0.f, 0.f); acc[i][1] = make_float2(0.f, 0.f); }

        if (t > 0) {
            int ph = (t - 1) & 1;
            if (wid == 0 && lane < 4) {
                asm volatile("fence.proxy.async;" ::: "memory");
                const float* src = g_ST2[(t + 1) & 1][r];
                uint32_t mb = mbar0 + lane * 8;
                mbar_expect_tx(mb, 16384u);
                uint32_t dst = (uint32_t)__cvta_generic_to_shared(st_s + lane * 4096);
                bulk_g2s(dst, src + lane * 4096, 16384u, mb);
            }
            mbar_wait(mymb, ph);
            const float* sp = st_s + kb * 16 + rg * 4;
            const float* wp = wh_s + kb * 32 + cg * 4;
            #pragma unroll
            for (int k = 0; k < 64; ++k) {
                float4 s4 = *reinterpret_cast<const float4*>(sp); sp += 16;
                float4 wq = *reinterpret_cast<const float4*>(wp); wp += 32;
                float2 w0 = make_float2(wq.x, wq.y);
                float2 w1 = make_float2(wq.z, wq.w);
                acc[0][0] = ffma2(dup2(s4.x), w0, acc[0][0]);
                acc[0][1] = ffma2(dup2(s4.x), w1, acc[0][1]);
                acc[1][0] = ffma2(dup2(s4.y), w0, acc[1][0]);
                acc[1][1] = ffma2(dup2(s4.y), w1, acc[1][1]);
                acc[2][0] = ffma2(dup2(s4.z), w0, acc[2][0]);
                acc[2][1] = ffma2(dup2(s4.z), w1, acc[2][1]);
                acc[3][0] = ffma2(dup2(s4.w), w0, acc[3][0]);
                acc[3][1] = ffma2(dup2(s4.w), w1, acc[3][1]);
            }
        }

        // cross-warp reduction of 16 K-split partials
        float* rp = red_s + wid * 512 + (rg * 4) * 32 + cg * 4;
        #pragma unroll
        for (int i = 0; i < 4; i++) {
            *reinterpret_cast<float2*>(rp + i * 32)     = acc[i][0];
            *reinterpret_cast<float2*>(rp + i * 32 + 2) = acc[i][1];
        }
        __syncthreads();
        {
            float v = 0.f;
            #pragma unroll
            for (int w = 0; w < 16; w++) v += red_s[w * 512 + o];
            float s0 = tanhf(zq + v);
            zbase[(size_t)t * (BB * HH)] = s0;          // feeds kernel C (coalesced)
            fin[em * 33 + en] = s0;
        }
        __syncthreads();
        {
            // coalesced transposed store: g_ST2 addr = base + hl*16 + em2 = base + tid
            float a = fin[em2 * 33 + hl];
            g_ST2[t & 1][r][(size_t)(c * 32 + hl) * 16 + em2] = a;
        }
        group_barrier(r);
    }
}

// ---------------------------------------------------------------- Kernel C: out[b][t][o] = bout[o] + sum_h S[row][h] * Wout[h][o]
__global__ void __launch_bounds__(256) out_kernel(const float* __restrict__ Wout,
                                                  const float* __restrict__ bout,
                                                  float* __restrict__ out) {
    extern __shared__ float dsm[];
    float* ss = dsm;           // [2][128][32]
    float* ws = dsm + 8192;    // [2][32][128]
    int r0 = blockIdx.x * 128;
    int o0 = blockIdx.y * 128;
    int tid = threadIdx.x;
    int tt = tid >> 4, th = tid & 15;

    float2 acc[8][4];
    #pragma unroll
    for (int i = 0; i < 8; i++)
        #pragma unroll
        for (int j = 0; j < 4; j++) acc[i][j] = make_float2(0.f, 0.f);

    auto issue = [&](int ci, int buf) {
        int f0 = ci * 32;
        float* sd = ss + buf * 4096;
        float* wd = ws + buf * 4096;
        #pragma unroll
        for (int it = 0; it < 4; it++) {
            int idx = it * 256 + tid;
            int ri = idx >> 3, kq = (idx & 7) * 4;
            cp_async16(sd + ri * 32 + kq, g_Z + (size_t)(r0 + ri) * HH + f0 + kq);
            int f = idx >> 5, u = (idx & 31) * 4;
            cp_async16(wd + f * 128 + u, Wout + (f0 + f) * OO + o0 + u);
        }
        cp_commit();
    };

    issue(0, 0);
    for (int ci = 0; ci < 32; ci++) {
        if (ci < 31) { issue(ci + 1, (ci + 1) & 1); cp_wait<1>(); }
        else cp_wait<0>();
        __syncthreads();
        const float* sc = ss + (ci & 1) * 4096;
        const float* wc = ws + (ci & 1) * 4096;
        #pragma unroll
        for (int k = 0; k < 32; k++) {
            float av[8];
            #pragma unroll
            for (int i = 0; i < 8; i++) av[i] = sc[(tt * 8 + i) * 32 + k];
            float4 w0 = *reinterpret_cast<const float4*>(wc + k * 128 + th * 8);
            float4 w1 = *reinterpret_cast<const float4*>(wc + k * 128 + th * 8 + 4);
            float2 wp[4] = { make_float2(w0.x, w0.y), make_float2(w0.z, w0.w),
                             make_float2(w1.x, w1.y), make_float2(w1.z, w1.w) };
            #pragma unroll
            for (int i = 0; i < 8; i++) {
                float2 ad = dup2(av[i]);
                #pragma unroll
                for (int j = 0; j < 4; j++) acc[i][j] = ffma2(ad, wp[j], acc[i][j]);
            }
        }
        __syncthreads();
    }
    float4 bv0 = *reinterpret_cast<const float4*>(bout + o0 + th * 8);
    float4 bv1 = *reinterpret_cast<const float4*>(bout + o0 + th * 8 + 4);
    #pragma unroll
    for (int i = 0; i < 8; i++) {
        int row = r0 + tt * 8 + i;
        int t  = row >> 6;
        int bb = row & 63;
        float* op = out + (size_t)bb * (TT * OO) + t * OO + o0 + th * 8;
        float4 q0 = make_float4(acc[i][0].x + bv0.x, acc[i][0].y + bv0.y,
                                acc[i][1].x + bv0.z, acc[i][1].y + bv0.w);
        float4 q1 = make_float4(acc[i][2].x + bv1.x, acc[i][2].y + bv1.y,
                                acc[i][3].x + bv1.z, acc[i][3].y + bv1.w);
        *reinterpret_cast<float4*>(op)     = q0;
        *reinterpret_cast<float4*>(op + 4) = q1;
    }
}

// ---------------------------------------------------------------- launch
extern "C" void kernel_launch(void* const* d_in, const int* in_sizes, int n_in,
                              void* d_out, int out_size) {
    const float* x    = (const float*)d_in[0];   // (B,F,T)
    const float* Wx   = (const float*)d_in[1];   // (F,H)
    const float* Wh   = (const float*)d_in[2];   // (H,H)
    const float* bv   = (const float*)d_in[3];   // (H,)
    const float* Wout = (const float*)d_in[4];   // (H,O)
    const float* bo   = (const float*)d_in[5];   // (O,)
    float* out = (float*)d_out;                  // (B,T,O)

    (void)in_sizes; (void)n_in; (void)out_size;

    // Phase 1: Z = x@Wx + b (parallel GEMM, double-buffered)
    cudaFuncSetAttribute(zmat_kernel, cudaFuncAttributeMaxDynamicSharedMemorySize, 65536);
    dim3 ga(TT / 128, HH / 128, BB);
    zmat_kernel<<<ga, 256, 65536>>>(x, Wx, bv);

    // Phase 2: persistent sequential recurrence (512 threads, 4 warps/SMSP)
    size_t dyn = (size_t)(16 + 32768 + 16384 + 8192 + 528) * sizeof(float);  // 231552 B
    cudaFuncSetAttribute(rnn_rec_kernel, cudaFuncAttributeMaxDynamicSharedMemorySize, 232448);
    rnn_rec_kernel<<<NB, 512, dyn>>>(Wh);

    // Phase 3: output projection (parallel GEMM, double-buffered)
    cudaFuncSetAttribute(out_kernel, cudaFuncAttributeMaxDynamicSharedMemorySize, 65536);
    dim3 gc((TT * BB) / 128, OO / 128);
    out_kernel<<<gc, 256, 65536>>>(Wout, bo, out);
}

// round 8
// speedup vs baseline: 1.1765x; 1.1765x over previous
#include <cuda_runtime.h>
#include <cuda_bf16.h>
#include <math.h>
#include <stdint.h>

#define BB 64
#define FF 256
#define TT 1024
#define HH 1024
#define OO 512
#define NB 128   // persistent CTAs: 4 batch-row groups x 32 H-col tiles

// Scratch (allocation-free rule: __device__ globals)
__device__ float g_Z[(size_t)TT * BB * HH];     // Z = x@Wx + b, later overwritten with states, [t][b][h]
__device__ float g_ST2[2][4][HH * 16];          // transposed state ping-pong, [buf][r-group][h][16 b]
__device__ unsigned g_flag[4 * 32 * 32];        // per-(r,c) generation flags, 128B apart

// ---------------------------------------------------------------- helpers
__device__ __forceinline__ float2 ffma2(float2 a, float2 b, float2 c) {
    unsigned long long ua = *reinterpret_cast<unsigned long long*>(&a);
    unsigned long long ub = *reinterpret_cast<unsigned long long*>(&b);
    unsigned long long uc = *reinterpret_cast<unsigned long long*>(&c);
    unsigned long long ud;
    asm("fma.rn.f32x2 %0, %1, %2, %3;" : "=l"(ud) : "l"(ua), "l"(ub), "l"(uc));
    return *reinterpret_cast<float2*>(&ud);
}
__device__ __forceinline__ float2 dup2(float s) { return make_float2(s, s); }

__device__ __forceinline__ void cp_async16(float* smem_dst, const float* gmem_src) {
    unsigned s = (unsigned)__cvta_generic_to_shared(smem_dst);
    asm volatile("cp.async.cg.shared.global [%0], [%1], 16;\n" :: "r"(s), "l"(gmem_src));
}
__device__ __forceinline__ void cp_commit() { asm volatile("cp.async.commit_group;\n"); }
template <int N> __device__ __forceinline__ void cp_wait() {
    asm volatile("cp.async.wait_group %0;\n" :: "n"(N));
}

__device__ __forceinline__ void mbar_init(uint32_t mb, uint32_t count) {
    asm volatile("mbarrier.init.shared.b64 [%0], %1;" :: "r"(mb), "r"(count) : "memory");
}
__device__ __forceinline__ void mbar_expect_tx(uint32_t mb, uint32_t bytes) {
    asm volatile("mbarrier.arrive.expect_tx.shared.b64 _, [%0], %1;" :: "r"(mb), "r"(bytes) : "memory");
}
__device__ __forceinline__ void bulk_g2s(uint32_t dst_smem, const float* src, uint32_t bytes, uint32_t mb) {
    asm volatile("cp.async.bulk.shared::cluster.global.mbarrier::complete_tx::bytes [%0], [%1], %2, [%3];"
                 :: "r"(dst_smem), "l"(src), "r"(bytes), "r"(mb) : "memory");
}
__device__ __forceinline__ void mbar_wait(uint32_t mb, int ph) {
    asm volatile(
        "{\n\t"
        ".reg .pred P;\n\t"
        "W%=:\n\t"
        "mbarrier.try_wait.parity.acquire.cta.shared::cta.b64 P, [%0], %1, 0x989680;\n\t"
        "@P bra D%=;\n\t"
        "bra W%=;\n\t"
        "D%=:\n\t"
        "}" :: "r"(mb), "r"(ph) : "memory");
}

__device__ __forceinline__ unsigned ld_acq_gpu(const unsigned* p) {
    unsigned v;
    asm volatile("ld.acquire.gpu.global.u32 %0, [%1];" : "=r"(v) : "l"(p) : "memory");
    return v;
}

// ---------------------------------------------------------------- reset: zero flags (stream-ordered before rec)
__global__ void reset_kernel() {
    for (int i = threadIdx.x; i < 4 * 32 * 32; i += blockDim.x) g_flag[i] = 0u;
}

// ---------------------------------------------------------------- Kernel A: Z[t][b][h] = b[h] + sum_f x[b][f][t] * Wx[f][h]
__global__ void __launch_bounds__(256) zmat_kernel(const float* __restrict__ x,
                                                   const float* __restrict__ Wx,
                                                   const float* __restrict__ bias) {
    extern __shared__ float dsm[];
    float* xs = dsm;           // [2][32][128]
    float* ws = dsm + 8192;    // [2][32][128]
    int t0 = blockIdx.x * 128;
    int h0 = blockIdx.y * 128;
    int b  = blockIdx.z;
    int tid = threadIdx.x;
    int tt = tid >> 4;
    int th = tid & 15;
    const float* xb = x + (size_t)b * FF * TT;

    float2 acc[8][4];
    #pragma unroll
    for (int i = 0; i < 8; i++)
        #pragma unroll
        for (int j = 0; j < 4; j++) acc[i][j] = make_float2(0.f, 0.f);

    auto issue = [&](int ci, int buf) {
        int f0 = ci * 32;
        float* xd = xs + buf * 4096;
        float* wd = ws + buf * 4096;
        #pragma unroll
        for (int it = 0; it < 4; it++) {
            int idx = it * 256 + tid;
            int f = idx >> 5, u = (idx & 31) * 4;
            cp_async16(xd + f * 128 + u, xb + (f0 + f) * TT + t0 + u);
            cp_async16(wd + f * 128 + u, Wx + (f0 + f) * HH + h0 + u);
        }
        cp_commit();
    };

    issue(0, 0);
    for (int ci = 0; ci < 8; ci++) {
        if (ci < 7) { issue(ci + 1, (ci + 1) & 1); cp_wait<1>(); }
        else cp_wait<0>();
        __syncthreads();
        const float* xc = xs + (ci & 1) * 4096;
        const float* wc = ws + (ci & 1) * 4096;
        #pragma unroll
        for (int k = 0; k < 32; k++) {
            float4 a0 = *reinterpret_cast<const float4*>(xc + k * 128 + tt * 8);
            float4 a1 = *reinterpret_cast<const float4*>(xc + k * 128 + tt * 8 + 4);
            float4 w0 = *reinterpret_cast<const float4*>(wc + k * 128 + th * 8);
            float4 w1 = *reinterpret_cast<const float4*>(wc + k * 128 + th * 8 + 4);
            float2 wp[4] = { make_float2(w0.x, w0.y), make_float2(w0.z, w0.w),
                             make_float2(w1.x, w1.y), make_float2(w1.z, w1.w) };
            float av[8] = { a0.x, a0.y, a0.z, a0.w, a1.x, a1.y, a1.z, a1.w };
            #pragma unroll
            for (int i = 0; i < 8; i++) {
                float2 ad = dup2(av[i]);
                #pragma unroll
                for (int j = 0; j < 4; j++) acc[i][j] = ffma2(ad, wp[j], acc[i][j]);
            }
        }
        __syncthreads();
    }
    float4 bv0 = *reinterpret_cast<const float4*>(bias + h0 + th * 8);
    float4 bv1 = *reinterpret_cast<const float4*>(bias + h0 + th * 8 + 4);
    #pragma unroll
    for (int i = 0; i < 8; i++) {
        int t = t0 + tt * 8 + i;
        float* zp = g_Z + (size_t)t * (BB * HH) + b * HH + h0 + th * 8;
        float4 o0 = make_float4(acc[i][0].x + bv0.x, acc[i][0].y + bv0.y,
                                acc[i][1].x + bv0.z, acc[i][1].y + bv0.w);
        float4 o1 = make_float4(acc[i][2].x + bv1.x, acc[i][2].y + bv1.y,
                                acc[i][3].x + bv1.z, acc[i][3].y + bv1.w);
        *reinterpret_cast<float4*>(zp)     = o0;
        *reinterpret_cast<float4*>(zp + 4) = o1;
    }
}

// ---------------------------------------------------------------- Kernel B: persistent recurrence — barrier-free dataflow
// 128 CTAs: (r in 0..3: 16 batch rows) x (c in 0..31: 32 H cols).
// 512 threads, K-split 16: warp w -> chunk ch=w>>2, quarter q=w&3, 64 k each.
// Staging warps (w&3)==0 poll their chunk's 8 producer flags (ld.acquire spin),
// then TMA the 16KB chunk. Flag gen t+1 (published after all reads of state t-1
// and writes of state t) doubles as read-ack -> 2-buffer ping-pong is race-free.
__global__ void __launch_bounds__(512, 1) rnn_rec_kernel(const float* __restrict__ Wh) {
    extern __shared__ float smem[];
    float* wh_s  = smem + 16;               // [k][32]  32768 floats (128KB)
    float* st_s  = wh_s + 32768;            // [k][16]  16384 floats (64KB)
    float* red_s = st_s + 16384;            // [16][512] 8192 floats (32KB)
    float* fin   = red_s + 8192;            // [16][33]   528 floats
    uint32_t mbar0 = (uint32_t)__cvta_generic_to_shared(smem);

    int tid  = threadIdx.x;
    int wid  = tid >> 5, lane = tid & 31;
    int c = blockIdx.x & 31;                // column tile (32 cols)
    int r = blockIdx.x >> 5;                // batch row group (16 rows)
    int r16 = r * 16;

    if (tid == 0) {
        #pragma unroll
        for (int ch = 0; ch < 4; ch++) mbar_init(mbar0 + ch * 8, 1);
    }
    for (int i = tid; i < 32768; i += 512) {
        int k = i >> 5, n = i & 31;
        wh_s[i] = Wh[k * HH + c * 32 + n];
    }
    __syncthreads();

    int rg = lane >> 3;                     // b-group: rows 4*rg..4*rg+3
    int cg = lane & 7;                      // h-group: cols 4*cg..4*cg+3
    int ch = wid >> 2;                      // chunk this warp consumes
    int kb = ch * 256 + (wid & 3) * 64;     // this warp's 64-k slice
    uint32_t mymb = mbar0 + ch * 8;
    bool stager = ((wid & 3) == 0);         // warps 0,4,8,12 stage chunk ch

    // epilogue: 1 output scalar per thread (512 outputs = 16b x 32h)
    int o  = tid;
    int em = o >> 5, en = o & 31;
    int brow = r16 + em, hcol = c * 32 + en;
    // transposed-store mapping
    int hl = tid >> 4, em2 = tid & 15;

    float* zbase = g_Z + (size_t)brow * HH + hcol;
    unsigned* myflag = &g_flag[(r * 32 + c) * 32];
    const unsigned* prodflag = &g_flag[(r * 32 + ch * 8 + (lane & 7)) * 32];

    for (int t = 0; t < TT; ++t) {
        float zq = zbase[(size_t)t * (BB * HH)];  // additive Z term (hidden behind FMA)

        float2 acc[4][2];
        #pragma unroll
        for (int i = 0; i < 4; i++) { acc[i][0] = make_float2(0.f, 0.f); acc[i][1] = make_float2(0.f, 0.f); }

        if (t > 0) {
            int ph = (t - 1) & 1;
            if (stager) {
                if (lane < 8) {
                    while (ld_acq_gpu(prodflag) < (unsigned)t) { }
                }
                __syncwarp();
                if (lane == 0) {
                    asm volatile("fence.proxy.async;" ::: "memory");
                    const float* src = g_ST2[(t + 1) & 1][r] + ch * 4096;
                    mbar_expect_tx(mymb, 16384u);
                    uint32_t dst = (uint32_t)__cvta_generic_to_shared(st_s + ch * 4096);
                    bulk_g2s(dst, src, 16384u, mymb);
                }
            }
            mbar_wait(mymb, ph);
            const float* sp = st_s + kb * 16 + rg * 4;
            const float* wp = wh_s + kb * 32 + cg * 4;
            #pragma unroll
            for (int k = 0; k < 64; ++k) {
                float4 s4 = *reinterpret_cast<const float4*>(sp); sp += 16;
                float4 wq = *reinterpret_cast<const float4*>(wp); wp += 32;
                float2 w0 = make_float2(wq.x, wq.y);
                float2 w1 = make_float2(wq.z, wq.w);
                acc[0][0] = ffma2(dup2(s4.x), w0, acc[0][0]);
                acc[0][1] = ffma2(dup2(s4.x), w1, acc[0][1]);
                acc[1][0] = ffma2(dup2(s4.y), w0, acc[1][0]);
                acc[1][1] = ffma2(dup2(s4.y), w1, acc[1][1]);
                acc[2][0] = ffma2(dup2(s4.z), w0, acc[2][0]);
                acc[2][1] = ffma2(dup2(s4.z), w1, acc[2][1]);
                acc[3][0] = ffma2(dup2(s4.w), w0, acc[3][0]);
                acc[3][1] = ffma2(dup2(s4.w), w1, acc[3][1]);
            }
        }

        // cross-warp reduction of 16 K-split partials
        float* rp = red_s + wid * 512 + (rg * 4) * 32 + cg * 4;
        #pragma unroll
        for (int i = 0; i < 4; i++) {
            *reinterpret_cast<float2*>(rp + i * 32)     = acc[i][0];
            *reinterpret_cast<float2*>(rp + i * 32 + 2) = acc[i][1];
        }
        __syncthreads();
        {
            float v = 0.f;
            #pragma unroll
            for (int w = 0; w < 16; w++) v += red_s[w * 512 + o];
            float s0 = tanhf(zq + v);
            zbase[(size_t)t * (BB * HH)] = s0;          // feeds kernel C (coalesced)
            fin[em * 33 + en] = s0;
        }
        __syncthreads();
        {
            // coalesced transposed store into the per-group slice
            float a = fin[em2 * 33 + hl];
            g_ST2[t & 1][r][(size_t)(c * 32 + hl) * 16 + em2] = a;
        }
        __syncthreads();   // all state STGs ordered before the release below (+ st_s reuse safety)
        if (tid == 0) {
            asm volatile("fence.acq_rel.gpu;" ::: "memory");
            unsigned g = (unsigned)(t + 1);
            asm volatile("st.relaxed.gpu.global.u32 [%0], %1;" :: "l"(myflag), "r"(g) : "memory");
        }
    }
}

// ---------------------------------------------------------------- Kernel C: out[b][t][o] = bout[o] + sum_h S[row][h] * Wout[h][o]
__global__ void __launch_bounds__(256) out_kernel(const float* __restrict__ Wout,
                                                  const float* __restrict__ bout,
                                                  float* __restrict__ out) {
    extern __shared__ float dsm[];
    float* ss = dsm;           // [2][128][32]
    float* ws = dsm + 8192;    // [2][32][128]
    int r0 = blockIdx.x * 128;
    int o0 = blockIdx.y * 128;
    int tid = threadIdx.x;
    int tt = tid >> 4, th = tid & 15;

    float2 acc[8][4];
    #pragma unroll
    for (int i = 0; i < 8; i++)
        #pragma unroll
        for (int j = 0; j < 4; j++) acc[i][j] = make_float2(0.f, 0.f);

    auto issue = [&](int ci, int buf) {
        int f0 = ci * 32;
        float* sd = ss + buf * 4096;
        float* wd = ws + buf * 4096;
        #pragma unroll
        for (int it = 0; it < 4; it++) {
            int idx = it * 256 + tid;
            int ri = idx >> 3, kq = (idx & 7) * 4;
            cp_async16(sd + ri * 32 + kq, g_Z + (size_t)(r0 + ri) * HH + f0 + kq);
            int f = idx >> 5, u = (idx & 31) * 4;
            cp_async16(wd + f * 128 + u, Wout + (f0 + f) * OO + o0 + u);
        }
        cp_commit();
    };

    issue(0, 0);
    for (int ci = 0; ci < 32; ci++) {
        if (ci < 31) { issue(ci + 1, (ci + 1) & 1); cp_wait<1>(); }
        else cp_wait<0>();
        __syncthreads();
        const float* sc = ss + (ci & 1) * 4096;
        const float* wc = ws + (ci & 1) * 4096;
        #pragma unroll
        for (int k = 0; k < 32; k++) {
            float av[8];
            #pragma unroll
            for (int i = 0; i < 8; i++) av[i] = sc[(tt * 8 + i) * 32 + k];
            float4 w0 = *reinterpret_cast<const float4*>(wc + k * 128 + th * 8);
            float4 w1 = *reinterpret_cast<const float4*>(wc + k * 128 + th * 8 + 4);
            float2 wp[4] = { make_float2(w0.x, w0.y), make_float2(w0.z, w0.w),
                             make_float2(w1.x, w1.y), make_float2(w1.z, w1.w) };
            #pragma unroll
            for (int i = 0; i < 8; i++) {
                float2 ad = dup2(av[i]);
                #pragma unroll
                for (int j = 0; j < 4; j++) acc[i][j] = ffma2(ad, wp[j], acc[i][j]);
            }
        }
        __syncthreads();
    }
    float4 bv0 = *reinterpret_cast<const float4*>(bout + o0 + th * 8);
    float4 bv1 = *reinterpret_cast<const float4*>(bout + o0 + th * 8 + 4);
    #pragma unroll
    for (int i = 0; i < 8; i++) {
        int row = r0 + tt * 8 + i;
        int t  = row >> 6;
        int bb = row & 63;
        float* op = out + (size_t)bb * (TT * OO) + t * OO + o0 + th * 8;
        float4 q0 = make_float4(acc[i][0].x + bv0.x, acc[i][0].y + bv0.y,
                                acc[i][1].x + bv0.z, acc[i][1].y + bv0.w);
        float4 q1 = make_float4(acc[i][2].x + bv1.x, acc[i][2].y + bv1.y,
                                acc[i][3].x + bv1.z, acc[i][3].y + bv1.w);
        *reinterpret_cast<float4*>(op)     = q0;
        *reinterpret_cast<float4*>(op + 4) = q1;
    }
}

// ---------------------------------------------------------------- launch
extern "C" void kernel_launch(void* const* d_in, const int* in_sizes, int n_in,
                              void* d_out, int out_size) {
    const float* x    = (const float*)d_in[0];   // (B,F,T)
    const float* Wx   = (const float*)d_in[1];   // (F,H)
    const float* Wh   = (const float*)d_in[2];   // (H,H)
    const float* bv   = (const float*)d_in[3];   // (H,)
    const float* Wout = (const float*)d_in[4];   // (H,O)
    const float* bo   = (const float*)d_in[5];   // (O,)
    float* out = (float*)d_out;                  // (B,T,O)

    (void)in_sizes; (void)n_in; (void)out_size;

    // Phase 0: reset dataflow flags (stream-ordered before the recurrence)
    reset_kernel<<<1, 256>>>();

    // Phase 1: Z = x@Wx + b (parallel GEMM, double-buffered)
    cudaFuncSetAttribute(zmat_kernel, cudaFuncAttributeMaxDynamicSharedMemorySize, 65536);
    dim3 ga(TT / 128, HH / 128, BB);
    zmat_kernel<<<ga, 256, 65536>>>(x, Wx, bv);

    // Phase 2: persistent sequential recurrence (barrier-free dataflow)
    size_t dyn = (size_t)(16 + 32768 + 16384 + 8192 + 528) * sizeof(float);  // 231552 B
    cudaFuncSetAttribute(rnn_rec_kernel, cudaFuncAttributeMaxDynamicSharedMemorySize, 232448);
    rnn_rec_kernel<<<NB, 512, dyn>>>(Wh);

    // Phase 3: output projection (parallel GEMM, double-buffered)
    cudaFuncSetAttribute(out_kernel, cudaFuncAttributeMaxDynamicSharedMemorySize, 65536);
    dim3 gc((TT * BB) / 128, OO / 128);
    out_kernel<<<gc, 256, 65536>>>(Wout, bo, out);
}

// round 9
// speedup vs baseline: 1.1961x; 1.0167x over previous
#include <cuda_runtime.h>
#include <cuda_bf16.h>
#include <math.h>
#include <stdint.h>

#define BB 64
#define FF 256
#define TT 1024
#define HH 1024
#define OO 512
#define NB 128   // persistent CTAs: 4 batch-row groups x 32 H-col tiles

// Scratch (allocation-free rule: __device__ globals)
__device__ float g_Z[(size_t)TT * BB * HH];     // Z = x@Wx + b, later overwritten with states, [t][b][h]
__device__ float g_ST2[2][4][HH * 16];          // transposed state ping-pong, [buf][r-group][h][16 b]
__device__ unsigned g_flag[4 * 32 * 32];        // per-(r,c) generation flags, 128B apart

// ---------------------------------------------------------------- helpers
__device__ __forceinline__ float2 ffma2(float2 a, float2 b, float2 c) {
    unsigned long long ua = *reinterpret_cast<unsigned long long*>(&a);
    unsigned long long ub = *reinterpret_cast<unsigned long long*>(&b);
    unsigned long long uc = *reinterpret_cast<unsigned long long*>(&c);
    unsigned long long ud;
    asm("fma.rn.f32x2 %0, %1, %2, %3;" : "=l"(ud) : "l"(ua), "l"(ub), "l"(uc));
    return *reinterpret_cast<float2*>(&ud);
}
__device__ __forceinline__ float2 dup2(float s) { return make_float2(s, s); }

__device__ __forceinline__ void cp_async16(float* smem_dst, const float* gmem_src) {
    unsigned s = (unsigned)__cvta_generic_to_shared(smem_dst);
    asm volatile("cp.async.cg.shared.global [%0], [%1], 16;\n" :: "r"(s), "l"(gmem_src));
}
__device__ __forceinline__ void cp_commit() { asm volatile("cp.async.commit_group;\n"); }
template <int N> __device__ __forceinline__ void cp_wait() {
    asm volatile("cp.async.wait_group %0;\n" :: "n"(N));
}

__device__ __forceinline__ void mbar_init(uint32_t mb, uint32_t count) {
    asm volatile("mbarrier.init.shared.b64 [%0], %1;" :: "r"(mb), "r"(count) : "memory");
}
__device__ __forceinline__ void mbar_expect_tx(uint32_t mb, uint32_t bytes) {
    asm volatile("mbarrier.arrive.expect_tx.shared.b64 _, [%0], %1;" :: "r"(mb), "r"(bytes) : "memory");
}
__device__ __forceinline__ void mbar_arrive(uint32_t mb) {
    asm volatile("mbarrier.arrive.shared.b64 _, [%0];" :: "r"(mb) : "memory");
}
__device__ __forceinline__ void bulk_g2s(uint32_t dst_smem, const float* src, uint32_t bytes, uint32_t mb) {
    asm volatile("cp.async.bulk.shared::cluster.global.mbarrier::complete_tx::bytes [%0], [%1], %2, [%3];"
                 :: "r"(dst_smem), "l"(src), "r"(bytes), "r"(mb) : "memory");
}
__device__ __forceinline__ void mbar_wait(uint32_t mb, int ph) {
    asm volatile(
        "{\n\t"
        ".reg .pred P;\n\t"
        "W%=:\n\t"
        "mbarrier.try_wait.parity.acquire.cta.shared::cta.b64 P, [%0], %1, 0x989680;\n\t"
        "@P bra D%=;\n\t"
        "bra W%=;\n\t"
        "D%=:\n\t"
        "}" :: "r"(mb), "r"(ph) : "memory");
}

__device__ __forceinline__ unsigned ld_acq_gpu(const unsigned* p) {
    unsigned v;
    asm volatile("ld.acquire.gpu.global.u32 %0, [%1];" : "=r"(v) : "l"(p) : "memory");
    return v;
}
__device__ __forceinline__ void bar_named(int id, int cnt) {
    asm volatile("bar.sync %0, %1;" :: "r"(id), "r"(cnt) : "memory");
}

// ---------------------------------------------------------------- reset: zero flags (stream-ordered before rec)
__global__ void reset_kernel() {
    for (int i = threadIdx.x; i < 4 * 32 * 32; i += blockDim.x) g_flag[i] = 0u;
}

// ---------------------------------------------------------------- Kernel A: Z[t][b][h] = b[h] + sum_f x[b][f][t] * Wx[f][h]
__global__ void __launch_bounds__(256, 2) zmat_kernel(const float* __restrict__ x,
                                                      const float* __restrict__ Wx,
                                                      const float* __restrict__ bias) {
    extern __shared__ float dsm[];
    float* xs = dsm;           // [2][32][128]
    float* ws = dsm + 8192;    // [2][32][128]
    int t0 = blockIdx.x * 128;
    int h0 = blockIdx.y * 128;
    int b  = blockIdx.z;
    int tid = threadIdx.x;
    int tt = tid >> 4;
    int th = tid & 15;
    const float* xb = x + (size_t)b * FF * TT;

    float2 acc[8][4];
    #pragma unroll
    for (int i = 0; i < 8; i++)
        #pragma unroll
        for (int j = 0; j < 4; j++) acc[i][j] = make_float2(0.f, 0.f);

    auto issue = [&](int ci, int buf) {
        int f0 = ci * 32;
        float* xd = xs + buf * 4096;
        float* wd = ws + buf * 4096;
        #pragma unroll
        for (int it = 0; it < 4; it++) {
            int idx = it * 256 + tid;
            int f = idx >> 5, u = (idx & 31) * 4;
            cp_async16(xd + f * 128 + u, xb + (f0 + f) * TT + t0 + u);
            cp_async16(wd + f * 128 + u, Wx + (f0 + f) * HH + h0 + u);
        }
        cp_commit();
    };

    issue(0, 0);
    for (int ci = 0; ci < 8; ci++) {
        if (ci < 7) { issue(ci + 1, (ci + 1) & 1); cp_wait<1>(); }
        else cp_wait<0>();
        __syncthreads();
        const float* xc = xs + (ci & 1) * 4096;
        const float* wc = ws + (ci & 1) * 4096;
        #pragma unroll
        for (int k = 0; k < 32; k++) {
            float4 a0 = *reinterpret_cast<const float4*>(xc + k * 128 + tt * 8);
            float4 a1 = *reinterpret_cast<const float4*>(xc + k * 128 + tt * 8 + 4);
            float4 w0 = *reinterpret_cast<const float4*>(wc + k * 128 + th * 8);
            float4 w1 = *reinterpret_cast<const float4*>(wc + k * 128 + th * 8 + 4);
            float2 wp[4] = { make_float2(w0.x, w0.y), make_float2(w0.z, w0.w),
                             make_float2(w1.x, w1.y), make_float2(w1.z, w1.w) };
            float av[8] = { a0.x, a0.y, a0.z, a0.w, a1.x, a1.y, a1.z, a1.w };
            #pragma unroll
            for (int i = 0; i < 8; i++) {
                float2 ad = dup2(av[i]);
                #pragma unroll
                for (int j = 0; j < 4; j++) acc[i][j] = ffma2(ad, wp[j], acc[i][j]);
            }
        }
        __syncthreads();
    }
    float4 bv0 = *reinterpret_cast<const float4*>(bias + h0 + th * 8);
    float4 bv1 = *reinterpret_cast<const float4*>(bias + h0 + th * 8 + 4);
    #pragma unroll
    for (int i = 0; i < 8; i++) {
        int t = t0 + tt * 8 + i;
        float* zp = g_Z + (size_t)t * (BB * HH) + b * HH + h0 + th * 8;
        float4 o0 = make_float4(acc[i][0].x + bv0.x, acc[i][0].y + bv0.y,
                                acc[i][1].x + bv0.z, acc[i][1].y + bv0.w);
        float4 o1 = make_float4(acc[i][2].x + bv1.x, acc[i][2].y + bv1.y,
                                acc[i][3].x + bv1.z, acc[i][3].y + bv1.w);
        *reinterpret_cast<float4*>(zp)     = o0;
        *reinterpret_cast<float4*>(zp + 4) = o1;
    }
}

// ---------------------------------------------------------------- Kernel B: persistent recurrence — warp-specialized dataflow
// 128 CTAs: (r in 0..3: 16 batch rows) x (c in 0..31: 32 H cols).
// 384 threads: warps 0-7 compute (2/SMSP), warps 8-11 dedicated stagers (poll flags + TMA).
// Compute: K-split 16 (thread tid<256: slice s=tid>>4, 64 k), per-thread tile 4b x 8h.
// Per-chunk full (TMA done) / consumed (reads done) mbarriers decouple staging from the
// compute warps' reduction barriers -> detect+TMA overlaps the consumer tail.
__global__ void __launch_bounds__(384, 1) rnn_rec_kernel(const float* __restrict__ Wh) {
    extern __shared__ float smem[];
    // [0..16 floats): 8 mbarriers: full[4] @ +0, consumed[4] @ +32B
    float* wh_s  = smem + 16;               // [k][32]  32768 floats (128KB)
    float* st_s  = wh_s + 32768;            // [k][16]  16384 floats (64KB)
    float* red_s = st_s + 16384;            // [16][512] 8192 floats (32KB)
    float* fin   = red_s + 8192;            // [16][33]   528 floats
    uint32_t mbar0 = (uint32_t)__cvta_generic_to_shared(smem);

    int tid  = threadIdx.x;
    int wid  = tid >> 5, lane = tid & 31;
    int c = blockIdx.x & 31;                // column tile (32 cols)
    int r = blockIdx.x >> 5;                // batch row group (16 rows)
    int r16 = r * 16;

    if (tid == 0) {
        #pragma unroll
        for (int ch = 0; ch < 4; ch++) {
            mbar_init(mbar0 + ch * 8, 1);        // full: TMA expect_tx
            mbar_init(mbar0 + 32 + ch * 8, 2);   // consumed: 2 compute warps arrive
        }
    }
    for (int i = tid; i < 32768; i += 384) {
        int k = i >> 5, n = i & 31;
        wh_s[i] = Wh[k * HH + c * 32 + n];
    }
    __syncthreads();   // last block-wide sync; warps diverge below

    unsigned* myflag = &g_flag[(r * 32 + c) * 32];

    if (wid >= 8) {
        // ---------------- stager warps: one chunk each, free-running
        int ch = wid - 8;
        uint32_t fullmb = mbar0 + ch * 8;
        uint32_t consmb = mbar0 + 32 + ch * 8;
        const unsigned* pf = &g_flag[(r * 32 + ch * 8 + (lane & 7)) * 32];
        for (int t = 1; t < TT; ++t) {
            if (t >= 2) mbar_wait(consmb, t & 1);          // reads of step t-1 done
            if (lane < 8) {
                while (ld_acq_gpu(pf) < (unsigned)t) { __nanosleep(32); }
            }
            __syncwarp();
            if (lane == 0) {
                asm volatile("fence.proxy.async;" ::: "memory");
                const float* src = g_ST2[(t + 1) & 1][r] + ch * 4096;
                mbar_expect_tx(fullmb, 16384u);
                uint32_t dst = (uint32_t)__cvta_generic_to_shared(st_s + ch * 4096);
                bulk_g2s(dst, src, 16384u, fullmb);
            }
        }
        return;
    }

    // ---------------- compute warps (threads 0..255)
    int s  = tid >> 4;            // k-slice 0..15, 64 k each
    int i4 = tid & 15;
    int rb = i4 >> 2;             // b-quad: rows 4*rb..4*rb+3
    int hc = i4 & 3;              // h-oct: cols 8*hc..8*hc+7
    int ch = s >> 2;              // chunk of this thread's slice (warp-uniform: wid>>1)
    uint32_t fullmb = mbar0 + ch * 8;
    uint32_t consmb = mbar0 + 32 + ch * 8;

    // epilogue: 2 outputs per thread
    int o  = tid * 2;
    int em = o >> 5, en = o & 31;
    int brow = r16 + em, hcol = c * 32 + en;
    int j2 = tid * 2;
    int hl = j2 >> 4, em2 = j2 & 15;

    float* zbase = g_Z + (size_t)brow * HH + hcol;

    for (int t = 0; t < TT; ++t) {
        float2 zq = *reinterpret_cast<const float2*>(zbase + (size_t)t * (BB * HH));

        float2 acc[4][4];
        #pragma unroll
        for (int bi = 0; bi < 4; bi++)
            #pragma unroll
            for (int j = 0; j < 4; j++) acc[bi][j] = make_float2(0.f, 0.f);

        if (t > 0) {
            mbar_wait(fullmb, (t - 1) & 1);
            const float* sp = st_s + (s * 64) * 16 + rb * 4;
            const float* wp = wh_s + (s * 64) * 32 + hc * 8;
            #pragma unroll 8
            for (int k = 0; k < 64; ++k) {
                float4 s4 = *reinterpret_cast<const float4*>(sp); sp += 16;
                float4 wq0 = *reinterpret_cast<const float4*>(wp);
                float4 wq1 = *reinterpret_cast<const float4*>(wp + 4); wp += 32;
                float2 w0 = make_float2(wq0.x, wq0.y);
                float2 w1 = make_float2(wq0.z, wq0.w);
                float2 w2 = make_float2(wq1.x, wq1.y);
                float2 w3 = make_float2(wq1.z, wq1.w);
                float sv[4] = { s4.x, s4.y, s4.z, s4.w };
                #pragma unroll
                for (int bi = 0; bi < 4; bi++) {
                    float2 ad = dup2(sv[bi]);
                    acc[bi][0] = ffma2(ad, w0, acc[bi][0]);
                    acc[bi][1] = ffma2(ad, w1, acc[bi][1]);
                    acc[bi][2] = ffma2(ad, w2, acc[bi][2]);
                    acc[bi][3] = ffma2(ad, w3, acc[bi][3]);
                }
            }
            __syncwarp();
            if (lane == 0) mbar_arrive(consmb);   // chunk readable->overwritable by stager
        }

        // partials: [slice s][output]
        {
            float* rp = red_s + s * 512 + (rb * 4) * 32 + hc * 8;
            #pragma unroll
            for (int bi = 0; bi < 4; bi++) {
                float4 p0 = make_float4(acc[bi][0].x, acc[bi][0].y, acc[bi][1].x, acc[bi][1].y);
                float4 p1 = make_float4(acc[bi][2].x, acc[bi][2].y, acc[bi][3].x, acc[bi][3].y);
                *reinterpret_cast<float4*>(rp + bi * 32)     = p0;
                *reinterpret_cast<float4*>(rp + bi * 32 + 4) = p1;
            }
        }
        bar_named(1, 256);
        float s0, s1;
        {
            float2 v = make_float2(0.f, 0.f);
            #pragma unroll
            for (int w = 0; w < 16; w++) {
                float2 p = *reinterpret_cast<const float2*>(red_s + w * 512 + o);
                v.x += p.x; v.y += p.y;
            }
            s0 = tanhf(zq.x + v.x);
            s1 = tanhf(zq.y + v.y);
            fin[em * 33 + en]     = s0;
            fin[em * 33 + en + 1] = s1;
        }
        bar_named(1, 256);
        {
            // coalesced transposed store into the per-group slice
            float a  = fin[em2 * 33 + hl];
            float b2 = fin[(em2 + 1) * 33 + hl];
            float* stp = g_ST2[t & 1][r] + (size_t)(c * 32 + hl) * 16 + em2;
            *reinterpret_cast<float2*>(stp) = make_float2(a, b2);
        }
        bar_named(1, 256);    // pre-fence barrier: all state STGs ordered before release
        if (tid == 0) {
            asm volatile("fence.acq_rel.gpu;" ::: "memory");
            unsigned g = (unsigned)(t + 1);
            asm volatile("st.relaxed.gpu.global.u32 [%0], %1;" :: "l"(myflag), "r"(g) : "memory");
        }
        // g_Z store off the inter-CTA critical path (feeds kernel C only)
        *reinterpret_cast<float2*>(zbase + (size_t)t * (BB * HH)) = make_float2(s0, s1);
    }
}

// ---------------------------------------------------------------- Kernel C: out[b][t][o] = bout[o] + sum_h S[row][h] * Wout[h][o]
__global__ void __launch_bounds__(256, 2) out_kernel(const float* __restrict__ Wout,
                                                     const float* __restrict__ bout,
                                                     float* __restrict__ out) {
    extern __shared__ float dsm[];
    float* ss = dsm;           // [2][128][32]
    float* ws = dsm + 8192;    // [2][32][128]
    int r0 = blockIdx.x * 128;
    int o0 = blockIdx.y * 128;
    int tid = threadIdx.x;
    int tt = tid >> 4, th = tid & 15;

    float2 acc[8][4];
    #pragma unroll
    for (int i = 0; i < 8; i++)
        #pragma unroll
        for (int j = 0; j < 4; j++) acc[i][j] = make_float2(0.f, 0.f);

    auto issue = [&](int ci, int buf) {
        int f0 = ci * 32;
        float* sd = ss + buf * 4096;
        float* wd = ws + buf * 4096;
        #pragma unroll
        for (int it = 0; it < 4; it++) {
            int idx = it * 256 + tid;
            int ri = idx >> 3, kq = (idx & 7) * 4;
            cp_async16(sd + ri * 32 + kq, g_Z + (size_t)(r0 + ri) * HH + f0 + kq);
            int f = idx >> 5, u = (idx & 31) * 4;
            cp_async16(wd + f * 128 + u, Wout + (f0 + f) * OO + o0 + u);
        }
        cp_commit();
    };

    issue(0, 0);
    for (int ci = 0; ci < 32; ci++) {
        if (ci < 31) { issue(ci + 1, (ci + 1) & 1); cp_wait<1>(); }
        else cp_wait<0>();
        __syncthreads();
        const float* sc = ss + (ci & 1) * 4096;
        const float* wc = ws + (ci & 1) * 4096;
        #pragma unroll
        for (int k = 0; k < 32; k++) {
            float av[8];
            #pragma unroll
            for (int i = 0; i < 8; i++) av[i] = sc[(tt * 8 + i) * 32 + k];
            float4 w0 = *reinterpret_cast<const float4*>(wc + k * 128 + th * 8);
            float4 w1 = *reinterpret_cast<const float4*>(wc + k * 128 + th * 8 + 4);
            float2 wp[4] = { make_float2(w0.x, w0.y), make_float2(w0.z, w0.w),
                             make_float2(w1.x, w1.y), make_float2(w1.z, w1.w) };
            #pragma unroll
            for (int i = 0; i < 8; i++) {
                float2 ad = dup2(av[i]);
                #pragma unroll
                for (int j = 0; j < 4; j++) acc[i][j] = ffma2(ad, wp[j], acc[i][j]);
            }
        }
        __syncthreads();
    }
    float4 bv0 = *reinterpret_cast<const float4*>(bout + o0 + th * 8);
    float4 bv1 = *reinterpret_cast<const float4*>(bout + o0 + th * 8 + 4);
    #pragma unroll
    for (int i = 0; i < 8; i++) {
        int row = r0 + tt * 8 + i;
        int t  = row >> 6;
        int bb = row & 63;
        float* op = out + (size_t)bb * (TT * OO) + t * OO + o0 + th * 8;
        float4 q0 = make_float4(acc[i][0].x + bv0.x, acc[i][0].y + bv0.y,
                                acc[i][1].x + bv0.z, acc[i][1].y + bv0.w);
        float4 q1 = make_float4(acc[i][2].x + bv1.x, acc[i][2].y + bv1.y,
                                acc[i][3].x + bv1.z, acc[i][3].y + bv1.w);
        *reinterpret_cast<float4*>(op)     = q0;
        *reinterpret_cast<float4*>(op + 4) = q1;
    }
}

// ---------------------------------------------------------------- launch
extern "C" void kernel_launch(void* const* d_in, const int* in_sizes, int n_in,
                              void* d_out, int out_size) {
    const float* x    = (const float*)d_in[0];   // (B,F,T)
    const float* Wx   = (const float*)d_in[1];   // (F,H)
    const float* Wh   = (const float*)d_in[2];   // (H,H)
    const float* bv   = (const float*)d_in[3];   // (H,)
    const float* Wout = (const float*)d_in[4];   // (H,O)
    const float* bo   = (const float*)d_in[5];   // (O,)
    float* out = (float*)d_out;                  // (B,T,O)

    (void)in_sizes; (void)n_in; (void)out_size;

    // Phase 0: reset dataflow flags (stream-ordered before the recurrence)
    reset_kernel<<<1, 256>>>();

    // Phase 1: Z = x@Wx + b (parallel GEMM, double-buffered, 2 CTAs/SM)
    cudaFuncSetAttribute(zmat_kernel, cudaFuncAttributeMaxDynamicSharedMemorySize, 65536);
    dim3 ga(TT / 128, HH / 128, BB);
    zmat_kernel<<<ga, 256, 65536>>>(x, Wx, bv);

    // Phase 2: persistent sequential recurrence (warp-specialized dataflow)
    size_t dyn = (size_t)(16 + 32768 + 16384 + 8192 + 528) * sizeof(float);  // 231552 B
    cudaFuncSetAttribute(rnn_rec_kernel, cudaFuncAttributeMaxDynamicSharedMemorySize, 232448);
    rnn_rec_kernel<<<NB, 384, dyn>>>(Wh);

    // Phase 3: output projection (parallel GEMM, double-buffered, 2 CTAs/SM)
    cudaFuncSetAttribute(out_kernel, cudaFuncAttributeMaxDynamicSharedMemorySize, 65536);
    dim3 gc((TT * BB) / 128, OO / 128);
    out_kernel<<<gc, 256, 65536>>>(Wout, bo, out);
}